// round 8
// baseline (speedup 1.0000x reference)
#include <cuda_runtime.h>
#include <cuda_fp16.h>

#define NN 50000
#define NE 1600000
#define TOT (NE + NN)
#define DIN 128
#define DH  64
#define NCHUNK 196           // ceil(NN/256)
#define BN_EPS 1e-5f
#define FXS 16777216.0f      // 2^24 fixed point for degree sum
#define MASK40 ((1ull << 40) - 1)

// ---------------- persistent scratch ----------------
__device__ int                g_src[NE];
__device__ unsigned int       g_dr[NE];        // (dst<<16)|rank
__device__ float              g_w[NE];
__device__ unsigned long long g_dc[NN];        // zero at entry (zeroed after read each run)
__device__ float              g_dinv[NN];
__device__ int                g_rowstart[NN];  // exclusive prefix within 256-chunk
__device__ int                g_bsum[NCHUNK];  // chunk offsets
__device__ __align__(16) int2    g_cv[TOT];
__device__ __align__(16) __half2 g_h[NN * (DH / 2)];
__device__ __align__(16) float   g_agg[NN * DH];
__device__ float g_sum1[DH], g_sq1[DH], g_sum2[DH], g_sq2[DH];   // zeroed in scan phase
__device__ int   g_is64;
__device__ unsigned          g_count;          // barrier arrivals (returns to 0)
__device__ volatile unsigned g_gen;            // barrier generation (monotonic)

// ---------------- f32x2 packed FMA (sm_10x FFMA2, PTX-only) ----------------
__device__ __forceinline__ unsigned long long bcast2(float x) {
    unsigned long long r; asm("mov.b64 %0, {%1,%1};" : "=l"(r) : "f"(x)); return r;
}
__device__ __forceinline__ void fma2(unsigned long long& d, unsigned long long a, unsigned long long b) {
    asm("fma.rn.f32x2 %0, %1, %2, %0;" : "+l"(d) : "l"(a), "l"(b));
}
__device__ __forceinline__ float2 unpack2(unsigned long long v) {
    float2 f; asm("mov.b64 {%0,%1}, %2;" : "=f"(f.x), "=f"(f.y) : "l"(v)); return f;
}

// ---------------- grid barrier (grid sized to guaranteed co-residency at launch) ----------------
__device__ __forceinline__ void gbar() {
    __threadfence();
    __syncthreads();
    if (threadIdx.x == 0) {
        unsigned gen = g_gen;
        if (atomicAdd(&g_count, 1) == gridDim.x - 1) {
            g_count = 0;
            __threadfence();
            g_gen = gen + 1;
        } else {
            while (g_gen == gen) __nanosleep(64);
            __threadfence();
        }
    }
    __syncthreads();
}

__device__ __forceinline__ int rowbeg(int i) { return g_rowstart[i] + g_bsum[i >> 8]; }

// ---------------- CSR gather aggregation phase (shared by both layers) ----------------
__device__ __forceinline__ void agg_phase(const float* __restrict__ bias,
                                          float* __restrict__ gsum, float* __restrict__ gsq,
                                          float* s_a, float* s_b) {
    const int tid = threadIdx.x;
    const int warp = tid >> 5, lane = tid & 31;
    if (tid < DH) { s_a[tid] = 0.f; s_b[tid] = 0.f; }
    __syncthreads();
    const __half2* hp = g_h;
    float bx = __ldg(&bias[2 * lane]);
    float by = __ldg(&bias[2 * lane + 1]);
    for (int row = blockIdx.x * 8 + warp; row < NN; row += gridDim.x * 8) {
        int beg = rowbeg(row);
        int end = (row == NN - 1) ? TOT : rowbeg(row + 1);
        float2 acc = {0.f, 0.f};
        int j = beg;
        for (; j + 4 <= end; j += 4) {
            int2 c0 = g_cv[j], c1 = g_cv[j + 1], c2 = g_cv[j + 2], c3 = g_cv[j + 3];
            float2 h0 = __half22float2(__ldcg(&hp[(size_t)c0.x * 32 + lane]));
            float2 h1 = __half22float2(__ldcg(&hp[(size_t)c1.x * 32 + lane]));
            float2 h2 = __half22float2(__ldcg(&hp[(size_t)c2.x * 32 + lane]));
            float2 h3 = __half22float2(__ldcg(&hp[(size_t)c3.x * 32 + lane]));
            float v0 = __int_as_float(c0.y), v1 = __int_as_float(c1.y);
            float v2 = __int_as_float(c2.y), v3 = __int_as_float(c3.y);
            acc.x += v0 * h0.x; acc.y += v0 * h0.y;
            acc.x += v1 * h1.x; acc.y += v1 * h1.y;
            acc.x += v2 * h2.x; acc.y += v2 * h2.y;
            acc.x += v3 * h3.x; acc.y += v3 * h3.y;
        }
        for (; j < end; ++j) {
            int2 c = g_cv[j];
            float2 hv = __half22float2(__ldcg(&hp[(size_t)c.x * 32 + lane]));
            float v = __int_as_float(c.y);
            acc.x += v * hv.x; acc.y += v * hv.y;
        }
        float di = g_dinv[row];
        acc.x = acc.x * di + bx;
        acc.y = acc.y * di + by;
        *(float2*)&g_agg[(size_t)row * DH + 2 * lane] = acc;
        atomicAdd(&s_a[2 * lane],     acc.x);
        atomicAdd(&s_a[2 * lane + 1], acc.y);
        atomicAdd(&s_b[2 * lane],     acc.x * acc.x);
        atomicAdd(&s_b[2 * lane + 1], acc.y * acc.y);
    }
    __syncthreads();
    if (tid < DH) {
        atomicAdd(&gsum[tid], s_a[tid]);
        atomicAdd(&gsq[tid],  s_b[tid]);
    }
}

// ---------------- the whole pipeline in one launch ----------------
__global__ void __launch_bounds__(256, 4)
k_all(const float* __restrict__ x, const void* __restrict__ ei,
      const float* __restrict__ wsc, const float* __restrict__ wfc,
      const float* __restrict__ alpha,
      const float* __restrict__ W1, const float* __restrict__ b1,
      const float* __restrict__ W2, const float* __restrict__ b2,
      const float* __restrict__ gamma1, const float* __restrict__ beta1,
      const float* __restrict__ gamma2, const float* __restrict__ beta2,
      float* __restrict__ out)
{
    __shared__ __align__(16) float sW[DIN * DH];   // 32 KB, reused per phase
    __shared__ float s_a[DH], s_b[DH];
    const int tid = threadIdx.x, bid = blockIdx.x, nb = gridDim.x;
    const int warp = tid >> 5, lane = tid & 31;

    // ---- phase 0: dtype probe ----
    if (bid == 0) {
        if (tid == 0) g_is64 = 1;
        __syncthreads();
        const int* p32 = (const int*)ei;
        int k = tid * (NE / 256);
        if (p32[2 * k + 1] != 0) g_is64 = 0;   // benign race: only writes 0
    }
    gbar();

    // ---- phase 1: gemm1  g_h = fp16(x @ W1) ----
    {
        for (int i = tid; i < DIN * DH; i += 256) sW[i] = W1[i];
        __syncthreads();
        for (int tile = bid; tile * 32 < NN; tile += nb) {
            int nbase = tile * 32 + warp * 4;
            if (nbase < NN) {
                int n0 = nbase, n1 = min(nbase + 1, NN - 1), n2 = min(nbase + 2, NN - 1), n3 = min(nbase + 3, NN - 1);
                const float4* x0 = (const float4*)(x + (size_t)n0 * DIN);
                const float4* x1 = (const float4*)(x + (size_t)n1 * DIN);
                const float4* x2 = (const float4*)(x + (size_t)n2 * DIN);
                const float4* x3 = (const float4*)(x + (size_t)n3 * DIN);
                unsigned long long a0 = 0ULL, a1 = 0ULL, a2 = 0ULL, a3 = 0ULL;
                #pragma unroll
                for (int kk = 0; kk < DIN / 4; ++kk) {
                    float ra[4], rb[4], rc[4], rd[4];
                    *(float4*)ra = __ldg(x0 + kk);
                    *(float4*)rb = __ldg(x1 + kk);
                    *(float4*)rc = __ldg(x2 + kk);
                    *(float4*)rd = __ldg(x3 + kk);
                    #pragma unroll
                    for (int u = 0; u < 4; ++u) {
                        unsigned long long w = *(const unsigned long long*)&sW[(4 * kk + u) * DH + 2 * lane];
                        fma2(a0, bcast2(ra[u]), w);
                        fma2(a1, bcast2(rb[u]), w);
                        fma2(a2, bcast2(rc[u]), w);
                        fma2(a3, bcast2(rd[u]), w);
                    }
                }
                g_h[(size_t)n0 * 32 + lane] = __float22half2_rn(unpack2(a0));
                if (nbase + 1 < NN) g_h[(size_t)n1 * 32 + lane] = __float22half2_rn(unpack2(a1));
                if (nbase + 2 < NN) g_h[(size_t)n2 * 32 + lane] = __float22half2_rn(unpack2(a2));
                if (nbase + 3 < NN) g_h[(size_t)n3 * 32 + lane] = __float22half2_rn(unpack2(a3));
            }
        }
    }
    gbar();

    // ---- phase 2: edge prep (one packed u64 atomic per edge) ----
    {
        float a = 1.f / (1.f + __expf(-__ldg(alpha)));
        int is64 = g_is64;
        for (int e = bid * 256 + tid; e < NE; e += nb * 256) {
            int s, d;
            if (is64) {
                const long long* p = (const long long*)ei;
                s = (int)__ldg(&p[e]);
                d = (int)__ldg(&p[NE + e]);
            } else {
                const int* p = (const int*)ei;
                s = __ldg(&p[e]);
                d = __ldg(&p[NE + e]);
            }
            s = min(max(s, 0), NN - 1);
            d = min(max(d, 0), NN - 1);
            float w = a * __ldg(&wsc[e]) + (1.f - a) * __ldg(&wfc[e]);
            unsigned long long wfx = (unsigned long long)(w * FXS + 0.5f);
            unsigned long long old = atomicAdd(&g_dc[d], (1ull << 40) | wfx);
            unsigned int rank = (unsigned int)(old >> 40) + 1u;   // rank 0 = self loop
            rank = min(rank, 65535u);
            g_src[e] = s;
            g_w[e]   = w;
            g_dr[e]  = ((unsigned int)d << 16) | rank;
        }
    }
    gbar();

    // ---- phase 3: scan pass 1 (256-chunks) + dinv + zero g_dc + zero stats ----
    {
        int* si = (int*)sW;
        for (int c = bid; c < NCHUNK; c += nb) {
            int i = c * 256 + tid;
            int v = 0; float deg = 1.0f;
            if (i < NN) {
                unsigned long long dc = g_dc[i];
                g_dc[i] = 0ull;                           // ready for next replay
                v = (int)(dc >> 40) + 1;                  // + self loop
                deg = 1.0f + (float)(dc & MASK40) * (1.0f / FXS);
            }
            si[tid] = v; __syncthreads();
            for (int off = 1; off < 256; off <<= 1) {
                int u = (tid >= off) ? si[tid - off] : 0;
                __syncthreads();
                si[tid] += u; __syncthreads();
            }
            if (i < NN) {
                g_rowstart[i] = si[tid] - v;              // exclusive within chunk
                g_dinv[i] = rsqrtf(deg);
            }
            if (tid == 255) g_bsum[c] = si[tid];
            __syncthreads();
        }
        if (bid == 0 && tid < DH) {
            g_sum1[tid] = 0.f; g_sq1[tid] = 0.f; g_sum2[tid] = 0.f; g_sq2[tid] = 0.f;
        }
    }
    gbar();

    // ---- phase 4: scan pass 2 (block 0 scans chunk sums) ----
    if (bid == 0) {
        int* si = (int*)sW;
        int v = (tid < NCHUNK) ? g_bsum[tid] : 0;
        si[tid] = v; __syncthreads();
        for (int off = 1; off < 256; off <<= 1) {
            int u = (tid >= off) ? si[tid - off] : 0;
            __syncthreads();
            si[tid] += u; __syncthreads();
        }
        if (tid < NCHUNK) g_bsum[tid] = si[tid] - v;      // exclusive chunk offsets
    }
    gbar();

    // ---- phase 5: CSR fill (atomic-free) ----
    for (int e = bid * 256 + tid; e < TOT; e += nb * 256) {
        if (e < NE) {
            unsigned int dr = g_dr[e];
            int d = (int)(dr >> 16);
            int rank = (int)(dr & 0xffffu);
            int s = g_src[e];
            int p = min(rowbeg(d) + rank, TOT - 1);
            g_cv[p] = make_int2(s, __float_as_int(g_dinv[s] * g_w[e]));
        } else {
            int i = e - NE;
            g_cv[rowbeg(i)] = make_int2(i, __float_as_int(g_dinv[i]));
        }
    }
    gbar();

    // ---- phase 6: agg layer 1 + stats ----
    agg_phase(b1, g_sum1, g_sq1, s_a, s_b);
    gbar();

    // ---- phase 7: gemm2  g_h = fp16(relu(bn1(g_agg)) @ W2) ----
    {
        for (int i = tid; i < DH * DH; i += 256) sW[i] = W2[i];
        if (tid < DH) {
            float mean = g_sum1[tid] * (1.f / NN);
            float var  = g_sq1[tid] * (1.f / NN) - mean * mean;
            float inv  = rsqrtf(var + BN_EPS);
            float sc   = __ldg(&gamma1[tid]) * inv;
            s_a[tid] = sc;
            s_b[tid] = __ldg(&beta1[tid]) - mean * sc;
        }
        __syncthreads();
        for (int tile = bid; tile * 32 < NN; tile += nb) {
            int nbase = tile * 32 + warp * 4;
            if (nbase < NN) {
                int n0 = nbase, n1 = min(nbase + 1, NN - 1), n2 = min(nbase + 2, NN - 1), n3 = min(nbase + 3, NN - 1);
                const float4* x0 = (const float4*)(g_agg + (size_t)n0 * DH);
                const float4* x1 = (const float4*)(g_agg + (size_t)n1 * DH);
                const float4* x2 = (const float4*)(g_agg + (size_t)n2 * DH);
                const float4* x3 = (const float4*)(g_agg + (size_t)n3 * DH);
                unsigned long long a0 = 0ULL, a1 = 0ULL, a2 = 0ULL, a3 = 0ULL;
                #pragma unroll
                for (int kk = 0; kk < DH / 4; ++kk) {
                    float ra[4], rb[4], rc[4], rd[4];
                    *(float4*)ra = __ldcg(x0 + kk);
                    *(float4*)rb = __ldcg(x1 + kk);
                    *(float4*)rc = __ldcg(x2 + kk);
                    *(float4*)rd = __ldcg(x3 + kk);
                    float scs[4], shs[4];
                    *(float4*)scs = *(float4*)&s_a[4 * kk];
                    *(float4*)shs = *(float4*)&s_b[4 * kk];
                    #pragma unroll
                    for (int u = 0; u < 4; ++u) {
                        unsigned long long w = *(const unsigned long long*)&sW[(4 * kk + u) * DH + 2 * lane];
                        float va = fmaxf(fmaf(ra[u], scs[u], shs[u]), 0.f);
                        float vb = fmaxf(fmaf(rb[u], scs[u], shs[u]), 0.f);
                        float vc = fmaxf(fmaf(rc[u], scs[u], shs[u]), 0.f);
                        float vd = fmaxf(fmaf(rd[u], scs[u], shs[u]), 0.f);
                        fma2(a0, bcast2(va), w);
                        fma2(a1, bcast2(vb), w);
                        fma2(a2, bcast2(vc), w);
                        fma2(a3, bcast2(vd), w);
                    }
                }
                g_h[(size_t)n0 * 32 + lane] = __float22half2_rn(unpack2(a0));
                if (nbase + 1 < NN) g_h[(size_t)n1 * 32 + lane] = __float22half2_rn(unpack2(a1));
                if (nbase + 2 < NN) g_h[(size_t)n2 * 32 + lane] = __float22half2_rn(unpack2(a2));
                if (nbase + 3 < NN) g_h[(size_t)n3 * 32 + lane] = __float22half2_rn(unpack2(a3));
            }
        }
    }
    gbar();

    // ---- phase 8: agg layer 2 + stats ----
    agg_phase(b2, g_sum2, g_sq2, s_a, s_b);
    gbar();

    // ---- phase 9: final  out = relu(bn2(g_agg)) ----
    {
        if (tid < DH) {
            float mean = g_sum2[tid] * (1.f / NN);
            float var  = g_sq2[tid] * (1.f / NN) - mean * mean;
            float inv  = rsqrtf(var + BN_EPS);
            float sc   = __ldg(&gamma2[tid]) * inv;
            s_a[tid] = sc;
            s_b[tid] = __ldg(&beta2[tid]) - mean * sc;
        }
        __syncthreads();
        for (int idx = bid * 256 + tid; idx < NN * (DH / 4); idx += nb * 256) {
            float4 v = __ldcg((const float4*)g_agg + idx);
            int cb = (idx & (DH / 4 - 1)) * 4;
            v.x = fmaxf(fmaf(v.x, s_a[cb + 0], s_b[cb + 0]), 0.f);
            v.y = fmaxf(fmaf(v.y, s_a[cb + 1], s_b[cb + 1]), 0.f);
            v.z = fmaxf(fmaf(v.z, s_a[cb + 2], s_b[cb + 2]), 0.f);
            v.w = fmaxf(fmaf(v.w, s_a[cb + 3], s_b[cb + 3]), 0.f);
            ((float4*)out)[idx] = v;
        }
    }
}

// ---------------- launch: ONE kernel, grid sized to measured co-residency ----------------
extern "C" void kernel_launch(void* const* d_in, const int* in_sizes, int n_in,
                              void* d_out, int out_size) {
    const float* x      = (const float*)d_in[0];
    const void*  ei_sc  = d_in[1];
    const float* wsc    = (const float*)d_in[2];
    // d_in[3] = edge_index_fc (unused by the reference math)
    const float* wfc    = (const float*)d_in[4];
    const float* alpha  = (const float*)d_in[5];
    const float* W1     = (const float*)d_in[6];
    const float* b1     = (const float*)d_in[7];
    const float* W2     = (const float*)d_in[8];
    const float* b2     = (const float*)d_in[9];
    const float* gamma1 = (const float*)d_in[10];
    const float* beta1  = (const float*)d_in[11];
    const float* gamma2 = (const float*)d_in[12];
    const float* beta2  = (const float*)d_in[13];
    float*       out    = (float*)d_out;

    static int nb = 0;
    if (!nb) {
        int sm = 148, maxb = 0;
        cudaDeviceGetAttribute(&sm, cudaDevAttrMultiProcessorCount, 0);
        // ACTUAL co-resident blocks/SM for this kernel (accounts for regs + static smem)
        cudaOccupancyMaxActiveBlocksPerMultiprocessor(&maxb, k_all, 256, 0);
        if (maxb < 1) maxb = 1;
        nb = sm * maxb;   // exactly one wave -> grid barrier is deadlock-free
    }
    k_all<<<nb, 256>>>(x, ei_sc, wsc, wfc, alpha, W1, b1, W2, b2,
                       gamma1, beta1, gamma2, beta2, out);
}